// round 2
// baseline (speedup 1.0000x reference)
#include <cuda_runtime.h>
#include <cstdint>
#include <cstddef>

// Problem constants (fixed shapes)
#define N_V   4000
#define N_E   16000
#define DDIM  64
#define NORD  5         // edge orders 0..4

// GEMM tiling
#define KSPLIT 8
#define KC     2000     // K per split  (16000/8)
#define KT     40       // K per chunk  (KC/KT = 50 chunks)
#define MT     128      // M tile
#define SA     44       // A smem row stride (conflict-free for frag loads)
#define SB     72       // B smem row stride (conflict-free for frag loads)
#define STAGES 3
#define NCHUNK 50
#define SUMBLK 64       // blocks in sums_kernel (deterministic partials)

// -------- device scratch (no allocations allowed) --------
__device__ float g_bsum[SUMBLK][6][64];           // per-block partial sums (deterministic)
__device__ float g_x0b[64];
__device__ float g_x1v[N_V * 64];
__device__ float g_x1e[N_E * 64];                 // tf32-rounded bits stored as float
__device__ float g_partial[KSPLIT][N_V * 64];

// ---------------------------------------------------------
// Bucket sums of x_e rows by order + sum of x_v rows.
// Each block writes its partials to a fixed slot -> fully deterministic.
__global__ __launch_bounds__(256) void sums_kernel(
    const float* __restrict__ x_v, const float* __restrict__ x_e,
    const int* __restrict__ orders)
{
    const int d = threadIdx.x & 63;
    const int sub = threadIdx.x >> 6;                       // 0..3
    const int g = (blockIdx.x << 2) | sub;                  // 0..255 row streams

    float av = 0.0f;
    for (int r = g; r < N_V; r += 256) av += x_v[(size_t)r * 64 + d];

    float a0 = 0, a1 = 0, a2 = 0, a3 = 0, a4 = 0;
    for (int r = g; r < N_E; r += 256) {
        float v = x_e[(size_t)r * 64 + d];
        int o = orders[r];
        if      (o == 0) a0 += v;
        else if (o == 1) a1 += v;
        else if (o == 2) a2 += v;
        else if (o == 3) a3 += v;
        else             a4 += v;
    }

    // reduce the 4 sub-streams within the block via shared memory (fixed order)
    __shared__ float red[4][6][64];
    red[sub][0][d] = av;
    red[sub][1][d] = a0;
    red[sub][2][d] = a1;
    red[sub][3][d] = a2;
    red[sub][4][d] = a3;
    red[sub][5][d] = a4;
    __syncthreads();
    if (sub < 6) {
        // thread (sub, d) reduces vector `sub` across the 4 sub-streams
        float s = red[0][sub][d] + red[1][sub][d] + red[2][sub][d] + red[3][sub][d];
        g_bsum[blockIdx.x][sub][d] = s;
    }
}

// x0b[d] = mean-row @ W[0,*] + b[d]   (deterministic reduction of g_bsum)
__global__ void x0b_kernel(const float* __restrict__ W, const float* __restrict__ b) {
    const int d = threadIdx.x;              // 64 threads
    __shared__ float sum[6][64];

    // reduce 64 block-partials in fixed order
    for (int v = 0; v < 6; v++) {
        float s = 0.0f;
        for (int blk = 0; blk < SUMBLK; blk++) s += g_bsum[blk][v][d];
        sum[v][d] = s;
    }
    __syncthreads();

    float acc = 0.0f;
    // vertices: order-1 weight W[0,1]
    for (int i = 0; i < 64; i++)
        acc += sum[0][i] * W[(size_t)1 * 4096 + i * 64 + d];
    // edges by bucket: W[0,k]
    for (int k = 0; k < NORD; k++)
        for (int i = 0; i < 64; i++)
            acc += sum[1 + k][i] * W[(size_t)k * 4096 + i * 64 + d];
    g_x0b[d] = acc * (1.0f / (float)(N_V + N_E)) + b[d];
}

// x1_v[r] = x_v[r] @ W[1,1];  x1_e[e] = x_e[e] @ W[1,k_e] (tf32-rounded)
// 16 rows per 256-thread block; 16 threads per row, 4 output dims per thread.
__global__ __launch_bounds__(256) void transform_kernel(
    const float* __restrict__ x_v, const float* __restrict__ x_e,
    const int* __restrict__ orders, const float* __restrict__ W)
{
    __shared__ float sx[16][64];
    const int tid = threadIdx.x;
    const int r0 = blockIdx.x * 16;

    // cooperative row load: 256 threads x float4 = 1024 floats = 16 rows
    {
        int lr = tid >> 4;
        int c4 = (tid & 15) * 4;
        int r = r0 + lr;
        const float* src = (r < N_V) ? (x_v + (size_t)r * 64 + c4)
                                     : (x_e + (size_t)(r - N_V) * 64 + c4);
        *(float4*)&sx[lr][c4] = *(const float4*)src;
    }
    __syncthreads();

    const int lr = tid >> 4;
    const int dq = (tid & 15) * 4;
    const int r = r0 + lr;
    int k = (r < N_V) ? 1 : orders[r - N_V];

    const float* w = W + (size_t)(NORD + k) * 4096 + dq;   // W[1][k][i][dq..dq+3]
    float a0 = 0, a1 = 0, a2 = 0, a3 = 0;
    #pragma unroll 8
    for (int i = 0; i < 64; i++) {
        float xi = sx[lr][i];
        float4 wv = *(const float4*)(w + (size_t)i * 64);
        a0 += xi * wv.x; a1 += xi * wv.y; a2 += xi * wv.z; a3 += xi * wv.w;
    }
    if (r < N_V) {
        float4 o; o.x = a0; o.y = a1; o.z = a2; o.w = a3;
        *(float4*)&g_x1v[(size_t)r * 64 + dq] = o;
    } else {
        uint32_t u0, u1, u2, u3;
        asm("cvt.rna.tf32.f32 %0, %1;" : "=r"(u0) : "f"(a0));
        asm("cvt.rna.tf32.f32 %0, %1;" : "=r"(u1) : "f"(a1));
        asm("cvt.rna.tf32.f32 %0, %1;" : "=r"(u2) : "f"(a2));
        asm("cvt.rna.tf32.f32 %0, %1;" : "=r"(u3) : "f"(a3));
        float4 o;
        o.x = __uint_as_float(u0); o.y = __uint_as_float(u1);
        o.z = __uint_as_float(u2); o.w = __uint_as_float(u3);
        *(float4*)&g_x1e[(size_t)(r - N_V) * 64 + dq] = o;
    }
}

// ---------------- main GEMM: partial[ks] = incidence_tile @ x1_e_chunk ----------------
__device__ __forceinline__ void mma_tf32(float* c, const uint32_t* a, const uint32_t* b) {
    asm volatile(
        "mma.sync.aligned.m16n8k8.row.col.f32.tf32.tf32.f32 "
        "{%0,%1,%2,%3}, {%4,%5,%6,%7}, {%8,%9}, {%0,%1,%2,%3};\n"
        : "+f"(c[0]), "+f"(c[1]), "+f"(c[2]), "+f"(c[3])
        : "r"(a[0]), "r"(a[1]), "r"(a[2]), "r"(a[3]), "r"(b[0]), "r"(b[1]));
}

__global__ __launch_bounds__(256) void gemm_kernel(const float* __restrict__ inc) {
    extern __shared__ float smem[];
    const int tid = threadIdx.x;
    const int m0 = blockIdx.x * MT;
    const int ks = blockIdx.y;
    const int kbase = ks * KC;

    auto loadStage = [&](int s, int kt) {
        float* sa = smem + s * (MT * SA + KT * SB);
        float* sb = sa + MT * SA;
        const int k0 = kbase + kt * KT;
        // A: 128 rows x 10 float4  (1280 ops, 5/thread)
        #pragma unroll
        for (int t = 0; t < 5; t++) {
            int id = tid + t * 256;
            int row = id / 10, c4 = id % 10;
            int gr = m0 + row; if (gr > N_V - 1) gr = N_V - 1;   // clamp (rows >=4000 unused)
            const float* gp = inc + (size_t)gr * N_E + k0 + c4 * 4;
            uint32_t sp = (uint32_t)__cvta_generic_to_shared(sa + row * SA + c4 * 4);
            asm volatile("cp.async.cg.shared.global [%0], [%1], 16;\n" :: "r"(sp), "l"(gp));
        }
        // B: 40 rows x 16 float4 (640 ops)
        #pragma unroll
        for (int t = 0; t < 3; t++) {
            int id = tid + t * 256;
            if (id < 640) {
                int row = id >> 4, c4 = (id & 15);
                const float* gp = g_x1e + (size_t)(k0 + row) * 64 + c4 * 4;
                uint32_t sp = (uint32_t)__cvta_generic_to_shared(sb + row * SB + c4 * 4);
                asm volatile("cp.async.cg.shared.global [%0], [%1], 16;\n" :: "r"(sp), "l"(gp));
            }
        }
        asm volatile("cp.async.commit_group;\n");
    };

    const int warp = tid >> 5, lane = tid & 31;
    const int wm = (warp & 3) * 32;   // 4 m-warps
    const int wn = (warp >> 2) * 32;  // 2 n-warps
    const int lg = lane >> 2;         // groupID
    const int lt = lane & 3;          // threadID_in_group

    float acc[2][4][4];
    #pragma unroll
    for (int mi = 0; mi < 2; mi++)
        #pragma unroll
        for (int ni = 0; ni < 4; ni++)
            #pragma unroll
            for (int q = 0; q < 4; q++) acc[mi][ni][q] = 0.0f;

    loadStage(0, 0);
    loadStage(1, 1);

    for (int kt = 0; kt < NCHUNK; kt++) {
        if (kt == NCHUNK - 1) asm volatile("cp.async.wait_group 0;\n");
        else                  asm volatile("cp.async.wait_group 1;\n");
        __syncthreads();
        if (kt + STAGES - 1 < NCHUNK) loadStage((kt + STAGES - 1) % STAGES, kt + STAGES - 1);

        const float* sa = smem + (kt % STAGES) * (MT * SA + KT * SB);
        const float* sb = sa + MT * SA;

        #pragma unroll
        for (int k8 = 0; k8 < KT / 8; k8++) {
            uint32_t afr[2][4], bfr[4][2];
            #pragma unroll
            for (int mi = 0; mi < 2; mi++) {
                int r = wm + mi * 16 + lg;
                int c = k8 * 8 + lt;
                float f0 = sa[r * SA + c];
                float f1 = sa[(r + 8) * SA + c];
                float f2 = sa[r * SA + c + 4];
                float f3 = sa[(r + 8) * SA + c + 4];
                asm("cvt.rna.tf32.f32 %0, %1;" : "=r"(afr[mi][0]) : "f"(f0));
                asm("cvt.rna.tf32.f32 %0, %1;" : "=r"(afr[mi][1]) : "f"(f1));
                asm("cvt.rna.tf32.f32 %0, %1;" : "=r"(afr[mi][2]) : "f"(f2));
                asm("cvt.rna.tf32.f32 %0, %1;" : "=r"(afr[mi][3]) : "f"(f3));
            }
            #pragma unroll
            for (int ni = 0; ni < 4; ni++) {
                int n = wn + ni * 8 + lg;
                int k = k8 * 8 + lt;
                bfr[ni][0] = __float_as_uint(sb[k * SB + n]);        // already tf32-rounded
                bfr[ni][1] = __float_as_uint(sb[(k + 4) * SB + n]);
            }
            #pragma unroll
            for (int mi = 0; mi < 2; mi++)
                #pragma unroll
                for (int ni = 0; ni < 4; ni++)
                    mma_tf32(acc[mi][ni], afr[mi], bfr[ni]);
        }
    }

    // write partials
    float* part = g_partial[ks];
    #pragma unroll
    for (int mi = 0; mi < 2; mi++) {
        int r = m0 + wm + mi * 16 + lg;
        #pragma unroll
        for (int ni = 0; ni < 4; ni++) {
            int n = wn + ni * 8 + 2 * lt;
            if (r < N_V) {
                float2 v; v.x = acc[mi][ni][0]; v.y = acc[mi][ni][1];
                *(float2*)&part[(size_t)r * 64 + n] = v;
            }
            if (r + 8 < N_V) {
                float2 v; v.x = acc[mi][ni][2]; v.y = acc[mi][ni][3];
                *(float2*)&part[(size_t)(r + 8) * 64 + n] = v;
            }
        }
    }
}

// out = (x1_v + sum partials) / (1+suffix) + x0b
__global__ __launch_bounds__(256) void epilogue_kernel(
    const float* __restrict__ suffix, float* __restrict__ out)
{
    int idx = blockIdx.x * 256 + threadIdx.x;
    int i = idx >> 6, d = idx & 63;
    float s = g_x1v[idx];
    #pragma unroll
    for (int p = 0; p < KSPLIT; p++) s += g_partial[p][idx];
    out[idx] = s / (1.0f + suffix[i]) + g_x0b[d];
}

// ---------------------------------------------------------
extern "C" void kernel_launch(void* const* d_in, const int* in_sizes, int n_in,
                              void* d_out, int out_size) {
    const float* x_v    = (const float*)d_in[0];
    const float* x_e    = (const float*)d_in[1];
    const float* inc    = (const float*)d_in[2];
    const int*   orders = (const int*)d_in[3];
    const float* suffix = (const float*)d_in[4];
    const float* W      = (const float*)d_in[5];
    const float* b      = (const float*)d_in[6];
    float* out = (float*)d_out;

    (void)in_sizes; (void)n_in; (void)out_size;

    sums_kernel<<<SUMBLK, 256>>>(x_v, x_e, orders);
    x0b_kernel<<<1, 64>>>(W, b);
    transform_kernel<<<(N_V + N_E) / 16, 256>>>(x_v, x_e, orders, W);

    size_t smem = (size_t)STAGES * (MT * SA + KT * SB) * sizeof(float);   // 102144 B
    cudaFuncSetAttribute((const void*)gemm_kernel,
                         cudaFuncAttributeMaxDynamicSharedMemorySize, (int)smem);
    gemm_kernel<<<dim3(32, KSPLIT), 256, smem>>>(inc);

    epilogue_kernel<<<(N_V * 64) / 256, 256>>>(suffix, out);
}

// round 3
// speedup vs baseline: 1.1235x; 1.1235x over previous
#include <cuda_runtime.h>
#include <cstdint>
#include <cstddef>

// Problem constants (fixed shapes)
#define N_V   4000
#define N_E   16000
#define DDIM  64
#define NORD  5         // edge orders 0..4

// GEMM tiling
#define KSPLIT 13       // splits 0..11: 1240 cols (31 chunks), split 12: 1120 (28 chunks)
#define KT     40       // K per chunk
#define MT     128      // M tile
#define SA     44       // A smem row stride (conflict-free for frag loads)
#define SB     72       // B smem row stride (conflict-free for frag loads)
#define STAGES 2
#define NBLK_T 1250     // transform blocks = (N_V+N_E)/16

// -------- device scratch (no allocations allowed) --------
__device__ float g_bsum[NBLK_T][6][64];           // per-block bucket partials (deterministic)
__device__ float g_x0b[64];
__device__ float g_x1v[N_V * 64];
__device__ float g_x1e[N_E * 64];                 // tf32-rounded bits stored as float
__device__ float g_partial[KSPLIT][N_V * 64];

// ---------------------------------------------------------
// Fused: per-row transform (x @ W[1,k]) + per-block bucket sums for the x0 mean.
// 16 rows per 256-thread block. Blocks 0..249 are pure-vertex, 250..1249 pure-edge.
__global__ __launch_bounds__(256) void transform_kernel(
    const float* __restrict__ x_v, const float* __restrict__ x_e,
    const int* __restrict__ orders, const float* __restrict__ W)
{
    __shared__ float sx[16][64];
    __shared__ int   sord[16];
    __shared__ float red[4][6][64];
    const int tid = threadIdx.x;
    const int r0 = blockIdx.x * 16;
    const bool isV = (r0 < N_V);

    // cooperative row load: 256 threads x float4 = 1024 floats = 16 rows
    {
        int lr = tid >> 4;
        int c4 = (tid & 15) * 4;
        int r = r0 + lr;
        const float* src = isV ? (x_v + (size_t)r * 64 + c4)
                               : (x_e + (size_t)(r - N_V) * 64 + c4);
        *(float4*)&sx[lr][c4] = *(const float4*)src;
    }
    if (tid < 16) sord[tid] = isV ? 1 : orders[r0 + tid - N_V];
    __syncthreads();

    // ---- fused bucket partial sums (for the global mean x0) ----
    {
        const int d = tid & 63, q = tid >> 6;        // q = 0..3, 4 rows each
        float a0 = 0, a1 = 0, a2 = 0, a3 = 0, a4 = 0, a5 = 0;
        #pragma unroll
        for (int j = 0; j < 4; j++) {
            int row = q * 4 + j;
            float v = sx[row][d];
            if (isV) a0 += v;
            else {
                int o = sord[row];
                if      (o == 0) a1 += v;
                else if (o == 1) a2 += v;
                else if (o == 2) a3 += v;
                else if (o == 3) a4 += v;
                else             a5 += v;
            }
        }
        red[q][0][d] = a0; red[q][1][d] = a1; red[q][2][d] = a2;
        red[q][3][d] = a3; red[q][4][d] = a4; red[q][5][d] = a5;
    }
    __syncthreads();
    if (tid < 64) {
        #pragma unroll
        for (int v = 0; v < 6; v++)
            g_bsum[blockIdx.x][v][tid] =
                red[0][v][tid] + red[1][v][tid] + red[2][v][tid] + red[3][v][tid];
    }

    // ---- per-row transform: 16 threads per row, 4 output dims per thread ----
    const int lr = tid >> 4;
    const int dq = (tid & 15) * 4;
    const int r = r0 + lr;
    const int k = sord[lr];

    const float* w = W + (size_t)(NORD + k) * 4096 + dq;   // W[1][k][i][dq..dq+3]
    float a0 = 0, a1 = 0, a2 = 0, a3 = 0;
    #pragma unroll 8
    for (int i = 0; i < 64; i++) {
        float xi = sx[lr][i];
        float4 wv = *(const float4*)(w + (size_t)i * 64);
        a0 += xi * wv.x; a1 += xi * wv.y; a2 += xi * wv.z; a3 += xi * wv.w;
    }
    if (isV) {
        float4 o; o.x = a0; o.y = a1; o.z = a2; o.w = a3;
        *(float4*)&g_x1v[(size_t)r * 64 + dq] = o;
    } else {
        uint32_t u0, u1, u2, u3;
        asm("cvt.rna.tf32.f32 %0, %1;" : "=r"(u0) : "f"(a0));
        asm("cvt.rna.tf32.f32 %0, %1;" : "=r"(u1) : "f"(a1));
        asm("cvt.rna.tf32.f32 %0, %1;" : "=r"(u2) : "f"(a2));
        asm("cvt.rna.tf32.f32 %0, %1;" : "=r"(u3) : "f"(a3));
        float4 o;
        o.x = __uint_as_float(u0); o.y = __uint_as_float(u1);
        o.z = __uint_as_float(u2); o.w = __uint_as_float(u3);
        *(float4*)&g_x1e[(size_t)(r - N_V) * 64 + dq] = o;
    }
}

// x0b[d] = mean-row @ W[0,*] + b[d]   (parallel deterministic reduction of g_bsum)
__global__ void x0b_kernel(const float* __restrict__ W, const float* __restrict__ b) {
    __shared__ float sum[6][64];
    __shared__ float part[6][64];
    const int tid = threadIdx.x;             // 384 threads
    const int v = tid >> 6, d = tid & 63;    // v = 0..5

    // reduce 1250 block-partials, fixed order, 5 ILP accumulators
    float s0 = 0, s1 = 0, s2 = 0, s3 = 0, s4 = 0;
    for (int blk = 0; blk < NBLK_T; blk += 5) {
        s0 += g_bsum[blk + 0][v][d];
        s1 += g_bsum[blk + 1][v][d];
        s2 += g_bsum[blk + 2][v][d];
        s3 += g_bsum[blk + 3][v][d];
        s4 += g_bsum[blk + 4][v][d];
    }
    sum[v][d] = ((s0 + s1) + (s2 + s3)) + s4;
    __syncthreads();

    // matvec: bucket v uses table (v==0 ? W[0,1] : W[0,v-1])
    const int table = (v == 0) ? 1 : (v - 1);
    const float* w = W + (size_t)table * 4096 + d;
    float acc = 0.0f;
    #pragma unroll 8
    for (int i = 0; i < 64; i++) acc += sum[v][i] * w[(size_t)i * 64];
    part[v][d] = acc;
    __syncthreads();

    if (tid < 64) {
        float t = part[0][tid] + part[1][tid] + part[2][tid]
                + part[3][tid] + part[4][tid] + part[5][tid];
        g_x0b[tid] = t * (1.0f / (float)(N_V + N_E)) + b[tid];
    }
}

// ---------------- main GEMM: partial[ks] = incidence_tile @ x1_e_chunk ----------------
__device__ __forceinline__ void mma_tf32(float* c, const uint32_t* a, const uint32_t* b) {
    asm volatile(
        "mma.sync.aligned.m16n8k8.row.col.f32.tf32.tf32.f32 "
        "{%0,%1,%2,%3}, {%4,%5,%6,%7}, {%8,%9}, {%0,%1,%2,%3};\n"
        : "+f"(c[0]), "+f"(c[1]), "+f"(c[2]), "+f"(c[3])
        : "r"(a[0]), "r"(a[1]), "r"(a[2]), "r"(a[3]), "r"(b[0]), "r"(b[1]));
}

__global__ __launch_bounds__(256, 3) void gemm_kernel(const float* __restrict__ inc) {
    extern __shared__ float smem[];
    const int tid = threadIdx.x;
    const int m0 = blockIdx.x * MT;
    const int ks = blockIdx.y;
    const int kbase = ks * 1240;                       // 12*1240 = 14880 for last split
    const int nchunk = (ks < 12) ? 31 : 28;            // 31*40=1240, 28*40=1120

    auto loadStage = [&](int s, int kt) {
        float* sa = smem + s * (MT * SA + KT * SB);
        float* sb = sa + MT * SA;
        const int k0 = kbase + kt * KT;
        // A: 128 rows x 10 float4  (1280 ops, 5/thread)
        #pragma unroll
        for (int t = 0; t < 5; t++) {
            int id = tid + t * 256;
            int row = id / 10, c4 = id % 10;
            int gr = m0 + row; if (gr > N_V - 1) gr = N_V - 1;   // clamp (rows >=4000 unused)
            const float* gp = inc + (size_t)gr * N_E + k0 + c4 * 4;
            uint32_t sp = (uint32_t)__cvta_generic_to_shared(sa + row * SA + c4 * 4);
            asm volatile("cp.async.cg.shared.global [%0], [%1], 16;\n" :: "r"(sp), "l"(gp));
        }
        // B: 40 rows x 16 float4 (640 ops)
        #pragma unroll
        for (int t = 0; t < 3; t++) {
            int id = tid + t * 256;
            if (id < 640) {
                int row = id >> 4, c4 = (id & 15);
                const float* gp = g_x1e + (size_t)(k0 + row) * 64 + c4 * 4;
                uint32_t sp = (uint32_t)__cvta_generic_to_shared(sb + row * SB + c4 * 4);
                asm volatile("cp.async.cg.shared.global [%0], [%1], 16;\n" :: "r"(sp), "l"(gp));
            }
        }
        asm volatile("cp.async.commit_group;\n");
    };

    const int warp = tid >> 5, lane = tid & 31;
    const int wm = (warp & 3) * 32;   // 4 m-warps
    const int wn = (warp >> 2) * 32;  // 2 n-warps
    const int lg = lane >> 2;         // groupID
    const int lt = lane & 3;          // threadID_in_group

    float acc[2][4][4];
    #pragma unroll
    for (int mi = 0; mi < 2; mi++)
        #pragma unroll
        for (int ni = 0; ni < 4; ni++)
            #pragma unroll
            for (int q = 0; q < 4; q++) acc[mi][ni][q] = 0.0f;

    loadStage(0, 0);
    loadStage(1, 1);

    for (int kt = 0; kt < nchunk; kt++) {
        if (kt == nchunk - 1) asm volatile("cp.async.wait_group 0;\n");
        else                  asm volatile("cp.async.wait_group 1;\n");
        __syncthreads();

        const float* sa = smem + (kt & 1) * (MT * SA + KT * SB);
        const float* sb = sa + MT * SA;

        #pragma unroll
        for (int k8 = 0; k8 < KT / 8; k8++) {
            uint32_t afr[2][4], bfr[4][2];
            #pragma unroll
            for (int mi = 0; mi < 2; mi++) {
                int r = wm + mi * 16 + lg;
                int c = k8 * 8 + lt;
                float f0 = sa[r * SA + c];
                float f1 = sa[(r + 8) * SA + c];
                float f2 = sa[r * SA + c + 4];
                float f3 = sa[(r + 8) * SA + c + 4];
                asm("cvt.rna.tf32.f32 %0, %1;" : "=r"(afr[mi][0]) : "f"(f0));
                asm("cvt.rna.tf32.f32 %0, %1;" : "=r"(afr[mi][1]) : "f"(f1));
                asm("cvt.rna.tf32.f32 %0, %1;" : "=r"(afr[mi][2]) : "f"(f2));
                asm("cvt.rna.tf32.f32 %0, %1;" : "=r"(afr[mi][3]) : "f"(f3));
            }
            #pragma unroll
            for (int ni = 0; ni < 4; ni++) {
                int n = wn + ni * 8 + lg;
                int k = k8 * 8 + lt;
                bfr[ni][0] = __float_as_uint(sb[k * SB + n]);        // already tf32-rounded
                bfr[ni][1] = __float_as_uint(sb[(k + 4) * SB + n]);
            }
            #pragma unroll
            for (int mi = 0; mi < 2; mi++)
                #pragma unroll
                for (int ni = 0; ni < 4; ni++)
                    mma_tf32(acc[mi][ni], afr[mi], bfr[ni]);
        }

        // refill the slot we just consumed (overlaps compute of kt+1)
        __syncthreads();
        if (kt + 2 < nchunk) loadStage(kt & 1, kt + 2);
    }

    // write partials
    float* part = g_partial[ks];
    #pragma unroll
    for (int mi = 0; mi < 2; mi++) {
        int r = m0 + wm + mi * 16 + lg;
        #pragma unroll
        for (int ni = 0; ni < 4; ni++) {
            int n = wn + ni * 8 + 2 * lt;
            if (r < N_V) {
                float2 v; v.x = acc[mi][ni][0]; v.y = acc[mi][ni][1];
                *(float2*)&part[(size_t)r * 64 + n] = v;
            }
            if (r + 8 < N_V) {
                float2 v; v.x = acc[mi][ni][2]; v.y = acc[mi][ni][3];
                *(float2*)&part[(size_t)(r + 8) * 64 + n] = v;
            }
        }
    }
}

// out = (x1_v + sum partials) / (1+suffix) + x0b
__global__ __launch_bounds__(256) void epilogue_kernel(
    const float* __restrict__ suffix, float* __restrict__ out)
{
    int idx = blockIdx.x * 256 + threadIdx.x;
    int i = idx >> 6, d = idx & 63;
    float s = g_x1v[idx];
    #pragma unroll
    for (int p = 0; p < KSPLIT; p++) s += g_partial[p][idx];
    out[idx] = s / (1.0f + suffix[i]) + g_x0b[d];
}

// ---------------------------------------------------------
extern "C" void kernel_launch(void* const* d_in, const int* in_sizes, int n_in,
                              void* d_out, int out_size) {
    const float* x_v    = (const float*)d_in[0];
    const float* x_e    = (const float*)d_in[1];
    const float* inc    = (const float*)d_in[2];
    const int*   orders = (const int*)d_in[3];
    const float* suffix = (const float*)d_in[4];
    const float* W      = (const float*)d_in[5];
    const float* b      = (const float*)d_in[6];
    float* out = (float*)d_out;

    (void)in_sizes; (void)n_in; (void)out_size;

    transform_kernel<<<NBLK_T, 256>>>(x_v, x_e, orders, W);
    x0b_kernel<<<1, 384>>>(W, b);

    size_t smem = (size_t)STAGES * (MT * SA + KT * SB) * sizeof(float);   // 68096 B
    cudaFuncSetAttribute((const void*)gemm_kernel,
                         cudaFuncAttributeMaxDynamicSharedMemorySize, (int)smem);
    gemm_kernel<<<dim3(32, KSPLIT), 256, smem>>>(inc);

    epilogue_kernel<<<(N_V * 64) / 256, 256>>>(suffix, out);
}

// round 4
// speedup vs baseline: 1.4518x; 1.2922x over previous
#include <cuda_runtime.h>
#include <cstdint>
#include <cstddef>

// Problem constants (fixed shapes)
#define N_V   4000
#define N_E   16000
#define DDIM  64
#define NORD  5         // edge orders 0..4

// GEMM tiling
#define KSPLIT 13       // splits 0..11: 1240 cols (31 chunks), split 12: 1120 (28 chunks)
#define KT     40       // K per chunk
#define MT     128      // M tile
#define SA     44       // A smem row stride (conflict-free for frag loads)
#define SB     72       // B smem row stride (conflict-free for frag loads)
#define STAGES 2
#define NBLK_T 1250     // transform blocks = (N_V+N_E)/16
#define RBLK   50       // stage-1 reduce blocks (1250 = 50*25)

// -------- device scratch (no allocations allowed) --------
__device__ float g_bsum[NBLK_T][6][64];           // per-block bucket partials (deterministic)
__device__ float g_bsum2[RBLK][6][64];            // stage-1 reduced partials
__device__ float g_x0b[64];
__device__ float g_x1v[N_V * 64];
__device__ float g_x1e[N_E * 64];                 // tf32-rounded bits stored as float
__device__ float g_partial[KSPLIT][N_V * 64];

// ---------------------------------------------------------
// Fused: per-row transform (x @ W[1,k]) + per-block bucket sums for the x0 mean.
// 16 rows per 256-thread block. Blocks 0..249 are pure-vertex, 250..1249 pure-edge.
__global__ __launch_bounds__(256) void transform_kernel(
    const float* __restrict__ x_v, const float* __restrict__ x_e,
    const int* __restrict__ orders, const float* __restrict__ W)
{
    __shared__ float sx[16][64];
    __shared__ int   sord[16];
    __shared__ float red[4][6][64];
    const int tid = threadIdx.x;
    const int r0 = blockIdx.x * 16;
    const bool isV = (r0 < N_V);

    // cooperative row load: 256 threads x float4 = 1024 floats = 16 rows
    {
        int lr = tid >> 4;
        int c4 = (tid & 15) * 4;
        int r = r0 + lr;
        const float* src = isV ? (x_v + (size_t)r * 64 + c4)
                               : (x_e + (size_t)(r - N_V) * 64 + c4);
        *(float4*)&sx[lr][c4] = *(const float4*)src;
    }
    if (tid < 16) sord[tid] = isV ? 1 : orders[r0 + tid - N_V];
    __syncthreads();

    // ---- fused bucket partial sums (for the global mean x0) ----
    {
        const int d = tid & 63, q = tid >> 6;        // q = 0..3, 4 rows each
        float a0 = 0, a1 = 0, a2 = 0, a3 = 0, a4 = 0, a5 = 0;
        #pragma unroll
        for (int j = 0; j < 4; j++) {
            int row = q * 4 + j;
            float v = sx[row][d];
            if (isV) a0 += v;
            else {
                int o = sord[row];
                if      (o == 0) a1 += v;
                else if (o == 1) a2 += v;
                else if (o == 2) a3 += v;
                else if (o == 3) a4 += v;
                else             a5 += v;
            }
        }
        red[q][0][d] = a0; red[q][1][d] = a1; red[q][2][d] = a2;
        red[q][3][d] = a3; red[q][4][d] = a4; red[q][5][d] = a5;
    }
    __syncthreads();
    if (tid < 64) {
        #pragma unroll
        for (int v = 0; v < 6; v++)
            g_bsum[blockIdx.x][v][tid] =
                red[0][v][tid] + red[1][v][tid] + red[2][v][tid] + red[3][v][tid];
    }

    // ---- per-row transform: 16 threads per row, 4 output dims per thread ----
    const int lr = tid >> 4;
    const int dq = (tid & 15) * 4;
    const int r = r0 + lr;
    const int k = sord[lr];

    const float* w = W + (size_t)(NORD + k) * 4096 + dq;   // W[1][k][i][dq..dq+3]
    float a0 = 0, a1 = 0, a2 = 0, a3 = 0;
    #pragma unroll 8
    for (int i = 0; i < 64; i++) {
        float xi = sx[lr][i];
        float4 wv = *(const float4*)(w + (size_t)i * 64);
        a0 += xi * wv.x; a1 += xi * wv.y; a2 += xi * wv.z; a3 += xi * wv.w;
    }
    if (isV) {
        float4 o; o.x = a0; o.y = a1; o.z = a2; o.w = a3;
        *(float4*)&g_x1v[(size_t)r * 64 + dq] = o;
    } else {
        uint32_t u0, u1, u2, u3;
        asm("cvt.rna.tf32.f32 %0, %1;" : "=r"(u0) : "f"(a0));
        asm("cvt.rna.tf32.f32 %0, %1;" : "=r"(u1) : "f"(a1));
        asm("cvt.rna.tf32.f32 %0, %1;" : "=r"(u2) : "f"(a2));
        asm("cvt.rna.tf32.f32 %0, %1;" : "=r"(u3) : "f"(a3));
        float4 o;
        o.x = __uint_as_float(u0); o.y = __uint_as_float(u1);
        o.z = __uint_as_float(u2); o.w = __uint_as_float(u3);
        *(float4*)&g_x1e[(size_t)(r - N_V) * 64 + dq] = o;
    }
}

// Stage-1 reduction: 50 blocks, each sums 25 fixed slices of g_bsum.
__global__ __launch_bounds__(384) void reduce_kernel() {
    const int tid = threadIdx.x;             // 384 = 6*64
    const int v = tid >> 6, d = tid & 63;
    const int base = blockIdx.x * 25;
    float s0 = 0, s1 = 0, s2 = 0, s3 = 0, s4 = 0;
    #pragma unroll
    for (int j = 0; j < 25; j += 5) {
        s0 += g_bsum[base + j + 0][v][d];
        s1 += g_bsum[base + j + 1][v][d];
        s2 += g_bsum[base + j + 2][v][d];
        s3 += g_bsum[base + j + 3][v][d];
        s4 += g_bsum[base + j + 4][v][d];
    }
    g_bsum2[blockIdx.x][v][d] = ((s0 + s1) + (s2 + s3)) + s4;
}

// x0b[d] = mean-row @ W[0,*] + b[d]   (reduce 50 partials, then 6 tiny matvecs)
__global__ void x0b_kernel(const float* __restrict__ W, const float* __restrict__ b) {
    __shared__ float sum[6][64];
    __shared__ float part[6][64];
    const int tid = threadIdx.x;             // 384 threads
    const int v = tid >> 6, d = tid & 63;    // v = 0..5

    float s0 = 0, s1 = 0, s2 = 0, s3 = 0, s4 = 0;
    #pragma unroll
    for (int blk = 0; blk < RBLK; blk += 5) {
        s0 += g_bsum2[blk + 0][v][d];
        s1 += g_bsum2[blk + 1][v][d];
        s2 += g_bsum2[blk + 2][v][d];
        s3 += g_bsum2[blk + 3][v][d];
        s4 += g_bsum2[blk + 4][v][d];
    }
    sum[v][d] = ((s0 + s1) + (s2 + s3)) + s4;
    __syncthreads();

    // matvec: bucket v uses table (v==0 ? W[0,1] : W[0,v-1])
    const int table = (v == 0) ? 1 : (v - 1);
    const float* w = W + (size_t)table * 4096 + d;
    float acc = 0.0f;
    #pragma unroll 8
    for (int i = 0; i < 64; i++) acc += sum[v][i] * w[(size_t)i * 64];
    part[v][d] = acc;
    __syncthreads();

    if (tid < 64) {
        float t = part[0][tid] + part[1][tid] + part[2][tid]
                + part[3][tid] + part[4][tid] + part[5][tid];
        g_x0b[tid] = t * (1.0f / (float)(N_V + N_E)) + b[tid];
    }
}

// ---------------- main GEMM: partial[ks] = incidence_tile @ x1_e_chunk ----------------
__device__ __forceinline__ void mma_tf32(float* c, const uint32_t* a, const uint32_t* b) {
    asm volatile(
        "mma.sync.aligned.m16n8k8.row.col.f32.tf32.tf32.f32 "
        "{%0,%1,%2,%3}, {%4,%5,%6,%7}, {%8,%9}, {%0,%1,%2,%3};\n"
        : "+f"(c[0]), "+f"(c[1]), "+f"(c[2]), "+f"(c[3])
        : "r"(a[0]), "r"(a[1]), "r"(a[2]), "r"(a[3]), "r"(b[0]), "r"(b[1]));
}

__global__ __launch_bounds__(256, 3) void gemm_kernel(const float* __restrict__ inc) {
    extern __shared__ float smem[];
    const int tid = threadIdx.x;
    const int m0 = blockIdx.x * MT;
    const int ks = blockIdx.y;
    const int kbase = ks * 1240;                       // 12*1240 = 14880 for last split
    const int nchunk = (ks < 12) ? 31 : 28;            // 31*40=1240, 28*40=1120

    auto loadStage = [&](int s, int kt) {
        float* sa = smem + s * (MT * SA + KT * SB);
        float* sb = sa + MT * SA;
        const int k0 = kbase + kt * KT;
        // A: 128 rows x 10 float4  (1280 ops, 5/thread)
        #pragma unroll
        for (int t = 0; t < 5; t++) {
            int id = tid + t * 256;
            int row = id / 10, c4 = id % 10;
            int gr = m0 + row; if (gr > N_V - 1) gr = N_V - 1;   // clamp (rows >=4000 unused)
            const float* gp = inc + (size_t)gr * N_E + k0 + c4 * 4;
            uint32_t sp = (uint32_t)__cvta_generic_to_shared(sa + row * SA + c4 * 4);
            asm volatile("cp.async.cg.shared.global [%0], [%1], 16;\n" :: "r"(sp), "l"(gp));
        }
        // B: 40 rows x 16 float4 (640 ops)
        #pragma unroll
        for (int t = 0; t < 3; t++) {
            int id = tid + t * 256;
            if (id < 640) {
                int row = id >> 4, c4 = (id & 15);
                const float* gp = g_x1e + (size_t)(k0 + row) * 64 + c4 * 4;
                uint32_t sp = (uint32_t)__cvta_generic_to_shared(sb + row * SB + c4 * 4);
                asm volatile("cp.async.cg.shared.global [%0], [%1], 16;\n" :: "r"(sp), "l"(gp));
            }
        }
        asm volatile("cp.async.commit_group;\n");
    };

    const int warp = tid >> 5, lane = tid & 31;
    const int wm = (warp & 3) * 32;   // 4 m-warps
    const int wn = (warp >> 2) * 32;  // 2 n-warps
    const int lg = lane >> 2;         // groupID
    const int lt = lane & 3;          // threadID_in_group

    float acc[2][4][4];
    #pragma unroll
    for (int mi = 0; mi < 2; mi++)
        #pragma unroll
        for (int ni = 0; ni < 4; ni++)
            #pragma unroll
            for (int q = 0; q < 4; q++) acc[mi][ni][q] = 0.0f;

    loadStage(0, 0);
    loadStage(1, 1);

    for (int kt = 0; kt < nchunk; kt++) {
        if (kt == nchunk - 1) asm volatile("cp.async.wait_group 0;\n");
        else                  asm volatile("cp.async.wait_group 1;\n");
        __syncthreads();

        const float* sa = smem + (kt & 1) * (MT * SA + KT * SB);
        const float* sb = sa + MT * SA;

        #pragma unroll
        for (int k8 = 0; k8 < KT / 8; k8++) {
            uint32_t afr[2][4], bfr[4][2];
            #pragma unroll
            for (int mi = 0; mi < 2; mi++) {
                int r = wm + mi * 16 + lg;
                int c = k8 * 8 + lt;
                float f0 = sa[r * SA + c];
                float f1 = sa[(r + 8) * SA + c];
                float f2 = sa[r * SA + c + 4];
                float f3 = sa[(r + 8) * SA + c + 4];
                asm("cvt.rna.tf32.f32 %0, %1;" : "=r"(afr[mi][0]) : "f"(f0));
                asm("cvt.rna.tf32.f32 %0, %1;" : "=r"(afr[mi][1]) : "f"(f1));
                asm("cvt.rna.tf32.f32 %0, %1;" : "=r"(afr[mi][2]) : "f"(f2));
                asm("cvt.rna.tf32.f32 %0, %1;" : "=r"(afr[mi][3]) : "f"(f3));
            }
            #pragma unroll
            for (int ni = 0; ni < 4; ni++) {
                int n = wn + ni * 8 + lg;
                int k = k8 * 8 + lt;
                bfr[ni][0] = __float_as_uint(sb[k * SB + n]);        // already tf32-rounded
                bfr[ni][1] = __float_as_uint(sb[(k + 4) * SB + n]);
            }
            #pragma unroll
            for (int mi = 0; mi < 2; mi++)
                #pragma unroll
                for (int ni = 0; ni < 4; ni++)
                    mma_tf32(acc[mi][ni], afr[mi], bfr[ni]);
        }

        // refill the slot we just consumed (overlaps compute of kt+1)
        __syncthreads();
        if (kt + 2 < nchunk) loadStage(kt & 1, kt + 2);
    }

    // write partials
    float* part = g_partial[ks];
    #pragma unroll
    for (int mi = 0; mi < 2; mi++) {
        int r = m0 + wm + mi * 16 + lg;
        #pragma unroll
        for (int ni = 0; ni < 4; ni++) {
            int n = wn + ni * 8 + 2 * lt;
            if (r < N_V) {
                float2 v; v.x = acc[mi][ni][0]; v.y = acc[mi][ni][1];
                *(float2*)&part[(size_t)r * 64 + n] = v;
            }
            if (r + 8 < N_V) {
                float2 v; v.x = acc[mi][ni][2]; v.y = acc[mi][ni][3];
                *(float2*)&part[(size_t)(r + 8) * 64 + n] = v;
            }
        }
    }
}

// out = (x1_v + sum partials) / (1+suffix) + x0b     (float4 per thread)
__global__ __launch_bounds__(256) void epilogue_kernel(
    const float* __restrict__ suffix, float* __restrict__ out)
{
    __shared__ float sx0b[64];
    if (threadIdx.x < 64) sx0b[threadIdx.x] = g_x0b[threadIdx.x];
    __syncthreads();

    int t4 = blockIdx.x * 256 + threadIdx.x;        // 0..63999
    int idx = t4 * 4;
    int i = idx >> 6, d = idx & 63;

    float4 s = *(const float4*)&g_x1v[idx];
    #pragma unroll
    for (int p = 0; p < KSPLIT; p++) {
        float4 v = *(const float4*)&g_partial[p][idx];
        s.x += v.x; s.y += v.y; s.z += v.z; s.w += v.w;
    }
    float inv = 1.0f / (1.0f + suffix[i]);
    float4 o;
    o.x = s.x * inv + sx0b[d + 0];
    o.y = s.y * inv + sx0b[d + 1];
    o.z = s.z * inv + sx0b[d + 2];
    o.w = s.w * inv + sx0b[d + 3];
    *(float4*)&out[idx] = o;
}

// ---------------------------------------------------------
extern "C" void kernel_launch(void* const* d_in, const int* in_sizes, int n_in,
                              void* d_out, int out_size) {
    const float* x_v    = (const float*)d_in[0];
    const float* x_e    = (const float*)d_in[1];
    const float* inc    = (const float*)d_in[2];
    const int*   orders = (const int*)d_in[3];
    const float* suffix = (const float*)d_in[4];
    const float* W      = (const float*)d_in[5];
    const float* b      = (const float*)d_in[6];
    float* out = (float*)d_out;

    (void)in_sizes; (void)n_in; (void)out_size;

    transform_kernel<<<NBLK_T, 256>>>(x_v, x_e, orders, W);
    reduce_kernel<<<RBLK, 384>>>();
    x0b_kernel<<<1, 384>>>(W, b);

    size_t smem = (size_t)STAGES * (MT * SA + KT * SB) * sizeof(float);   // 68096 B
    cudaFuncSetAttribute((const void*)gemm_kernel,
                         cudaFuncAttributeMaxDynamicSharedMemorySize, (int)smem);
    gemm_kernel<<<dim3(32, KSPLIT), 256, smem>>>(inc);

    epilogue_kernel<<<(N_V * 64) / 1024, 256>>>(suffix, out);
}